// round 4
// baseline (speedup 1.0000x reference)
#include <cuda_runtime.h>
#include <cstdint>
#include <math.h>

// Problem constants
#define SIZE_U   6000
#define SIZE_V   6000
#define N_TOTAL  12000
#define DIM      256
#define KTOP     20
#define ROW_LEN  12000
#define CAP      1024           // candidate buffer capacity (expected ~84 per row)

#define OUT_X    0ull                    // sigmoid(u_s @ v_s^T): 36,000,000 f32
#define OUT_US   36000000ull             // u_s: 1,536,000 f32
#define OUT_VS   37536000ull             // v_s: 1,536,000 f32

// ---------------------------------------------------------------------------
// Mask dtype detection. Reference mask is bool (N,1); harness may deliver it
// as packed bool (1B/elem), int32, or float32. int32/float32 are both just
// "32-bit word != 0"; only packed-bool differs. Scan first 3000 words
// (= 12000 bytes, in-bounds under every layout):
//   - any byte >= 2 anywhere                    -> word-per-element
//   - bytes all in {0,1} but upper bytes nonzero -> packed bool
//   - else                                       -> word-per-element
// ---------------------------------------------------------------------------
__device__ int g_mask_is_bool;

__global__ void detect_mask_kernel(const unsigned* __restrict__ m) {
    __shared__ int s_word, s_bool;
    if (threadIdx.x == 0) { s_word = 0; s_bool = 0; }
    __syncthreads();
    for (int i = threadIdx.x; i < 3000; i += blockDim.x) {
        unsigned w = m[i];
        if (w & 0xFEFEFEFEu)        atomicOr(&s_word, 1);   // some byte >= 2
        else if (w & 0xFFFFFF00u)   atomicOr(&s_bool, 1);   // bytes<=1, upper lanes set
    }
    __syncthreads();
    if (threadIdx.x == 0) g_mask_is_bool = (s_bool && !s_word) ? 1 : 0;
}

// ---------------------------------------------------------------------------
// Kernel 1: per-row top-20 of sim, weighted feature merge, mask select.
// One block (256 threads) per row. Masked rows copy the original feature and
// never read their sim row (halves HBM traffic). Unmasked rows: threshold scan
// collects candidates > 0.993 into smem (sim ~ U[0,1): E[cnt]=84, P[cnt<20]
// negligible); a robust slow path (20 global argmax sweeps) covers any other
// distribution, including candidate-buffer overflow.
// ---------------------------------------------------------------------------
__global__ __launch_bounds__(256)
void topk_merge_kernel(const float* __restrict__ u, const float* __restrict__ v,
                       const float* __restrict__ sim, const void* __restrict__ mask,
                       float* __restrict__ out)
{
    const int n   = blockIdx.x;
    const int tid = threadIdx.x;

    bool keep;
    if (g_mask_is_bool) keep = ((const unsigned char*)mask)[n] != 0;
    else                keep = ((const unsigned*)mask)[n]      != 0;

    const float* feat = (n < SIZE_U) ? (u + (size_t)n * DIM)
                                     : (v + (size_t)(n - SIZE_U) * DIM);
    float* dst = (n < SIZE_U) ? (out + OUT_US + (size_t)n * DIM)
                              : (out + OUT_VS + (size_t)(n - SIZE_U) * DIM);

    if (keep) { dst[tid] = feat[tid]; return; }

    __shared__ float s_cval[CAP];
    __shared__ int   s_cidx[CAP];
    __shared__ int   s_cnt;
    __shared__ float s_rval[256];
    __shared__ int   s_ridx[256];
    __shared__ float s_selv[KTOP];
    __shared__ int   s_seli[KTOP];
    __shared__ float s_wsum;

    const float T0 = 0.993f;
    const float4* row4 = (const float4*)(sim + (size_t)n * ROW_LEN);

    if (tid == 0) s_cnt = 0;
    __syncthreads();

    for (int i = tid; i < ROW_LEN / 4; i += 256) {
        float4 sv = row4[i];
        if (sv.x > T0) { int p = atomicAdd(&s_cnt, 1); if (p < CAP) { s_cval[p] = sv.x; s_cidx[p] = 4*i;   } }
        if (sv.y > T0) { int p = atomicAdd(&s_cnt, 1); if (p < CAP) { s_cval[p] = sv.y; s_cidx[p] = 4*i+1; } }
        if (sv.z > T0) { int p = atomicAdd(&s_cnt, 1); if (p < CAP) { s_cval[p] = sv.z; s_cidx[p] = 4*i+2; } }
        if (sv.w > T0) { int p = atomicAdd(&s_cnt, 1); if (p < CAP) { s_cval[p] = sv.w; s_cidx[p] = 4*i+3; } }
    }
    __syncthreads();
    const int cnt = s_cnt;

    if (cnt >= KTOP && cnt <= CAP) {
        // Fast path: 20 argmax rounds over <=CAP candidates in smem.
        // Tie-break: larger value wins; equal values -> smaller index (matches
        // jax.lax.top_k which returns first occurrence order).
        for (int j = 0; j < KTOP; j++) {
            float bv = -3e38f; int bi = 0x7fffffff;
            for (int c = tid; c < cnt; c += 256) {
                float vv = s_cval[c]; int ii = s_cidx[c];
                if (vv > bv || (vv == bv && ii < bi)) { bv = vv; bi = ii; }
            }
            s_rval[tid] = bv; s_ridx[tid] = bi;
            __syncthreads();
            for (int s = 128; s; s >>= 1) {
                if (tid < s) {
                    float v2 = s_rval[tid + s]; int i2 = s_ridx[tid + s];
                    if (v2 > s_rval[tid] || (v2 == s_rval[tid] && i2 < s_ridx[tid])) {
                        s_rval[tid] = v2; s_ridx[tid] = i2;
                    }
                }
                __syncthreads();
            }
            if (tid == 0) { s_selv[j] = s_rval[0]; s_seli[j] = s_ridx[0]; }
            int widx = s_ridx[0];
            for (int c = tid; c < cnt; c += 256)
                if (s_cidx[c] == widx) s_cval[c] = -2.0f;   // mark used
            __syncthreads();
        }
    } else {
        // Slow path (pathological data / overflow): 20 global argmax sweeps.
        const float* row = sim + (size_t)n * ROW_LEN;
        for (int j = 0; j < KTOP; j++) {
            float bv = -3e38f; int bi = 0x7fffffff;
            for (int i = tid; i < ROW_LEN; i += 256) {
                float vv = row[i];
                bool used = false;
                for (int q = 0; q < j; q++) if (s_seli[q] == i) used = true;
                if (!used && (vv > bv || (vv == bv && i < bi))) { bv = vv; bi = i; }
            }
            s_rval[tid] = bv; s_ridx[tid] = bi;
            __syncthreads();
            for (int s = 128; s; s >>= 1) {
                if (tid < s) {
                    float v2 = s_rval[tid + s]; int i2 = s_ridx[tid + s];
                    if (v2 > s_rval[tid] || (v2 == s_rval[tid] && i2 < s_ridx[tid])) {
                        s_rval[tid] = v2; s_ridx[tid] = i2;
                    }
                }
                __syncthreads();
            }
            if (tid == 0) { s_selv[j] = s_rval[0]; s_seli[j] = s_ridx[0]; }
            __syncthreads();
        }
    }

    if (tid == 0) {
        float s = 0.f;
        for (int q = 0; q < KTOP; q++) s += s_selv[q];
        s_wsum = s;
    }
    __syncthreads();

    // Weighted gather-merge: thread tid handles feature dim tid (DIM == blockDim).
    float acc = 0.f;
    #pragma unroll
    for (int q = 0; q < KTOP; q++) {
        int id = s_seli[q];
        const float* f = (id < SIZE_U) ? (u + (size_t)id * DIM)
                                       : (v + (size_t)(id - SIZE_U) * DIM);
        acc += s_selv[q] * f[tid];
    }
    dst[tid] = acc / s_wsum;
}

// ---------------------------------------------------------------------------
// Kernel 2: C = sigmoid(A @ B^T), A=u_s[6000,256], B=v_s[6000,256] (K-major).
// 128x128 block tile, BK=16, 8x8 per thread, fp32 FFMA, fused sigmoid.
// ---------------------------------------------------------------------------
#define BM 128
#define BN 128
#define BK 16
#define M6 6000

__global__ __launch_bounds__(256)
void gemm_sigmoid_kernel(const float* __restrict__ A, const float* __restrict__ B,
                         float* __restrict__ C)
{
    __shared__ float As[BK][BM];
    __shared__ float Bs[BK][BN];

    const int tid = threadIdx.x;
    const int tx = tid & 15;          // 0..15 -> 8 output cols each
    const int ty = tid >> 4;          // 0..15 -> 8 output rows each
    const int row0 = blockIdx.y * BM;
    const int col0 = blockIdx.x * BN;

    float acc[8][8];
    #pragma unroll
    for (int i = 0; i < 8; i++)
        #pragma unroll
        for (int j = 0; j < 8; j++) acc[i][j] = 0.f;

    for (int kc = 0; kc < DIM; kc += BK) {
        // Load A/B tiles: 128 rows x 16 k each = 512 float4 per tile, 2/thread.
        #pragma unroll
        for (int it = 0; it < 2; it++) {
            int l  = tid + it * 256;
            int r  = l >> 2;
            int kq = (l & 3) * 4;
            int gr = row0 + r;
            float4 av = make_float4(0.f, 0.f, 0.f, 0.f);
            if (gr < M6) av = *(const float4*)(A + (size_t)gr * DIM + kc + kq);
            As[kq + 0][r] = av.x; As[kq + 1][r] = av.y;
            As[kq + 2][r] = av.z; As[kq + 3][r] = av.w;

            int gc = col0 + r;
            float4 bv = make_float4(0.f, 0.f, 0.f, 0.f);
            if (gc < M6) bv = *(const float4*)(B + (size_t)gc * DIM + kc + kq);
            Bs[kq + 0][r] = bv.x; Bs[kq + 1][r] = bv.y;
            Bs[kq + 2][r] = bv.z; Bs[kq + 3][r] = bv.w;
        }
        __syncthreads();

        #pragma unroll
        for (int kk = 0; kk < BK; kk++) {
            float4 a0 = *(const float4*)&As[kk][ty * 8];
            float4 a1 = *(const float4*)&As[kk][ty * 8 + 4];
            float4 b0 = *(const float4*)&Bs[kk][tx * 8];
            float4 b1 = *(const float4*)&Bs[kk][tx * 8 + 4];
            float a[8] = {a0.x, a0.y, a0.z, a0.w, a1.x, a1.y, a1.z, a1.w};
            float b[8] = {b0.x, b0.y, b0.z, b0.w, b1.x, b1.y, b1.z, b1.w};
            #pragma unroll
            for (int i = 0; i < 8; i++)
                #pragma unroll
                for (int j = 0; j < 8; j++) acc[i][j] += a[i] * b[j];
        }
        __syncthreads();
    }

    // Fused sigmoid epilogue; float4 stores (6000 % 4 == 0 so per-4 guards OK).
    #pragma unroll
    for (int i = 0; i < 8; i++) {
        int r = row0 + ty * 8 + i;
        if (r >= M6) break;
        #pragma unroll
        for (int j4 = 0; j4 < 2; j4++) {
            int c = col0 + tx * 8 + j4 * 4;
            if (c >= M6) continue;
            float4 o;
            o.x = __fdividef(1.f, 1.f + __expf(-acc[i][j4 * 4 + 0]));
            o.y = __fdividef(1.f, 1.f + __expf(-acc[i][j4 * 4 + 1]));
            o.z = __fdividef(1.f, 1.f + __expf(-acc[i][j4 * 4 + 2]));
            o.w = __fdividef(1.f, 1.f + __expf(-acc[i][j4 * 4 + 3]));
            *(float4*)(C + (size_t)r * M6 + c) = o;
        }
    }
}

// ---------------------------------------------------------------------------
extern "C" void kernel_launch(void* const* d_in, const int* in_sizes, int n_in,
                              void* d_out, int out_size)
{
    const float* u   = (const float*)d_in[0];
    const float* v   = (const float*)d_in[1];
    const float* sim = (const float*)d_in[2];
    const void*  msk = d_in[3];
    float* out = (float*)d_out;

    detect_mask_kernel<<<1, 256>>>((const unsigned*)msk);
    topk_merge_kernel<<<N_TOTAL, 256>>>(u, v, sim, msk, out);

    dim3 g((M6 + BN - 1) / BN, (M6 + BM - 1) / BM);
    gemm_sigmoid_kernel<<<g, 256>>>(out + OUT_US, out + OUT_VS, out + OUT_X);
}

// round 6
// speedup vs baseline: 1.6533x; 1.6533x over previous
#include <cuda_runtime.h>
#include <cuda_bf16.h>
#include <cstdint>
#include <math.h>

// Problem constants
#define SIZE_U   6000
#define SIZE_V   6000
#define N_TOTAL  12000
#define DIM      256
#define KTOP     20
#define ROW_LEN  12000
#define CAP      1024

#define OUT_X    0ull
#define OUT_US   36000000ull
#define OUT_VS   37536000ull

// bf16 split scratch: row n in [0,12000) = concat(u_s, v_s), col in [0,256)
__device__ __nv_bfloat16 g_hi[(size_t)N_TOTAL * DIM];
__device__ __nv_bfloat16 g_lo[(size_t)N_TOTAL * DIM];

// ---------------------------------------------------------------------------
// Mask dtype detection (packed bool vs 32-bit word per element).
// ---------------------------------------------------------------------------
__device__ int g_mask_is_bool;

__global__ void detect_mask_kernel(const unsigned* __restrict__ m) {
    __shared__ int s_word, s_bool;
    if (threadIdx.x == 0) { s_word = 0; s_bool = 0; }
    __syncthreads();
    for (int i = threadIdx.x; i < 3000; i += blockDim.x) {
        unsigned w = m[i];
        if (w & 0xFEFEFEFEu)        atomicOr(&s_word, 1);
        else if (w & 0xFFFFFF00u)   atomicOr(&s_bool, 1);
    }
    __syncthreads();
    if (threadIdx.x == 0) g_mask_is_bool = (s_bool && !s_word) ? 1 : 0;
}

// ---------------------------------------------------------------------------
// Kernel 1: per-row top-20, weighted merge, mask select. Also emits the
// bf16 hi/lo split of the selected feature row into g_hi/g_lo for the GEMM.
// ---------------------------------------------------------------------------
__global__ __launch_bounds__(256)
void topk_merge_kernel(const float* __restrict__ u, const float* __restrict__ v,
                       const float* __restrict__ sim, const void* __restrict__ mask,
                       float* __restrict__ out)
{
    const int n   = blockIdx.x;
    const int tid = threadIdx.x;

    bool keep;
    if (g_mask_is_bool) keep = ((const unsigned char*)mask)[n] != 0;
    else                keep = ((const unsigned*)mask)[n]      != 0;

    const float* feat = (n < SIZE_U) ? (u + (size_t)n * DIM)
                                     : (v + (size_t)(n - SIZE_U) * DIM);
    float* dst = (n < SIZE_U) ? (out + OUT_US + (size_t)n * DIM)
                              : (out + OUT_VS + (size_t)(n - SIZE_U) * DIM);

    if (keep) {
        float x = feat[tid];
        dst[tid] = x;
        __nv_bfloat16 h = __float2bfloat16(x);
        g_hi[(size_t)n * DIM + tid] = h;
        g_lo[(size_t)n * DIM + tid] = __float2bfloat16(x - __bfloat162float(h));
        return;
    }

    __shared__ float s_cval[CAP];
    __shared__ int   s_cidx[CAP];
    __shared__ int   s_cnt;
    __shared__ float s_rval[256];
    __shared__ int   s_ridx[256];
    __shared__ float s_selv[KTOP];
    __shared__ int   s_seli[KTOP];
    __shared__ float s_wsum;

    const float T0 = 0.993f;
    const float4* row4 = (const float4*)(sim + (size_t)n * ROW_LEN);

    if (tid == 0) s_cnt = 0;
    __syncthreads();

    for (int i = tid; i < ROW_LEN / 4; i += 256) {
        float4 sv = row4[i];
        if (sv.x > T0) { int p = atomicAdd(&s_cnt, 1); if (p < CAP) { s_cval[p] = sv.x; s_cidx[p] = 4*i;   } }
        if (sv.y > T0) { int p = atomicAdd(&s_cnt, 1); if (p < CAP) { s_cval[p] = sv.y; s_cidx[p] = 4*i+1; } }
        if (sv.z > T0) { int p = atomicAdd(&s_cnt, 1); if (p < CAP) { s_cval[p] = sv.z; s_cidx[p] = 4*i+2; } }
        if (sv.w > T0) { int p = atomicAdd(&s_cnt, 1); if (p < CAP) { s_cval[p] = sv.w; s_cidx[p] = 4*i+3; } }
    }
    __syncthreads();
    const int cnt = s_cnt;

    if (cnt >= KTOP && cnt <= CAP) {
        for (int j = 0; j < KTOP; j++) {
            float bv = -3e38f; int bi = 0x7fffffff;
            for (int c = tid; c < cnt; c += 256) {
                float vv = s_cval[c]; int ii = s_cidx[c];
                if (vv > bv || (vv == bv && ii < bi)) { bv = vv; bi = ii; }
            }
            s_rval[tid] = bv; s_ridx[tid] = bi;
            __syncthreads();
            for (int s = 128; s; s >>= 1) {
                if (tid < s) {
                    float v2 = s_rval[tid + s]; int i2 = s_ridx[tid + s];
                    if (v2 > s_rval[tid] || (v2 == s_rval[tid] && i2 < s_ridx[tid])) {
                        s_rval[tid] = v2; s_ridx[tid] = i2;
                    }
                }
                __syncthreads();
            }
            if (tid == 0) { s_selv[j] = s_rval[0]; s_seli[j] = s_ridx[0]; }
            int widx = s_ridx[0];
            for (int c = tid; c < cnt; c += 256)
                if (s_cidx[c] == widx) s_cval[c] = -2.0f;
            __syncthreads();
        }
    } else {
        const float* row = sim + (size_t)n * ROW_LEN;
        for (int j = 0; j < KTOP; j++) {
            float bv = -3e38f; int bi = 0x7fffffff;
            for (int i = tid; i < ROW_LEN; i += 256) {
                float vv = row[i];
                bool used = false;
                for (int q = 0; q < j; q++) if (s_seli[q] == i) used = true;
                if (!used && (vv > bv || (vv == bv && i < bi))) { bv = vv; bi = i; }
            }
            s_rval[tid] = bv; s_ridx[tid] = bi;
            __syncthreads();
            for (int s = 128; s; s >>= 1) {
                if (tid < s) {
                    float v2 = s_rval[tid + s]; int i2 = s_ridx[tid + s];
                    if (v2 > s_rval[tid] || (v2 == s_rval[tid] && i2 < s_ridx[tid])) {
                        s_rval[tid] = v2; s_ridx[tid] = i2;
                    }
                }
                __syncthreads();
            }
            if (tid == 0) { s_selv[j] = s_rval[0]; s_seli[j] = s_ridx[0]; }
            __syncthreads();
        }
    }

    if (tid == 0) {
        float s = 0.f;
        for (int q = 0; q < KTOP; q++) s += s_selv[q];
        s_wsum = s;
    }
    __syncthreads();

    float acc = 0.f;
    #pragma unroll
    for (int q = 0; q < KTOP; q++) {
        int id = s_seli[q];
        const float* f = (id < SIZE_U) ? (u + (size_t)id * DIM)
                                       : (v + (size_t)(id - SIZE_U) * DIM);
        acc += s_selv[q] * f[tid];
    }
    float x = acc / s_wsum;
    dst[tid] = x;
    __nv_bfloat16 h = __float2bfloat16(x);
    g_hi[(size_t)n * DIM + tid] = h;
    g_lo[(size_t)n * DIM + tid] = __float2bfloat16(x - __bfloat162float(h));
}

// ---------------------------------------------------------------------------
// Kernel 2: C = sigmoid(A @ B^T) via bf16 split-fp32 mma.sync on the tensor
// pipe. A = rows [0,6000) of scratch, B = rows [6000,12000).
// D = Ahi*Bhi + Ahi*Blo + Alo*Bhi (fp32 accumulate); lo*lo term dropped.
// Tile: 128x128, BK=32, 8 warps (2x4), each warp 64x32 via m16n8k16.
// ---------------------------------------------------------------------------
#define M6   6000
#define GBM  128
#define GBN  128
#define GBK  32
#define LDT  40          // padded smem row stride (bf16 elems) -> conflict-free LDSM

__device__ __forceinline__ unsigned ssa(const void* p) {
    return (unsigned)__cvta_generic_to_shared(p);
}

__device__ __forceinline__ void ldsm4(unsigned addr, unsigned& d0, unsigned& d1,
                                      unsigned& d2, unsigned& d3) {
    asm volatile("ldmatrix.sync.aligned.m8n8.x4.shared.b16 {%0,%1,%2,%3}, [%4];"
                 : "=r"(d0), "=r"(d1), "=r"(d2), "=r"(d3) : "r"(addr));
}

__device__ __forceinline__ void mma16816(float* c, const unsigned* a, unsigned b0, unsigned b1) {
    asm volatile(
        "mma.sync.aligned.m16n8k16.row.col.f32.bf16.bf16.f32 "
        "{%0,%1,%2,%3}, {%4,%5,%6,%7}, {%8,%9}, {%0,%1,%2,%3};"
        : "+f"(c[0]), "+f"(c[1]), "+f"(c[2]), "+f"(c[3])
        : "r"(a[0]), "r"(a[1]), "r"(a[2]), "r"(a[3]), "r"(b0), "r"(b1));
}

__global__ __launch_bounds__(256)
void gemm_sigmoid_mma_kernel(float* __restrict__ C)
{
    __shared__ __nv_bfloat16 sAh[GBM][LDT];
    __shared__ __nv_bfloat16 sAl[GBM][LDT];
    __shared__ __nv_bfloat16 sBh[GBN][LDT];
    __shared__ __nv_bfloat16 sBl[GBN][LDT];

    const int tid  = threadIdx.x;
    const int lane = tid & 31;
    const int wid  = tid >> 5;
    const int wr   = (wid >> 2) * 64;   // warp row offset in tile: 0 / 64
    const int wc   = (wid & 3) * 32;    // warp col offset: 0/32/64/96
    const int row0 = blockIdx.y * GBM;
    const int col0 = blockIdx.x * GBN;

    float acc[4][4][4];
    #pragma unroll
    for (int i = 0; i < 4; i++)
        #pragma unroll
        for (int j = 0; j < 4; j++)
            #pragma unroll
            for (int q = 0; q < 4; q++) acc[i][j][q] = 0.f;

    // per-thread global->smem mapping: 8 threads per 32-wide row, 4 bf16 each
    const int lr = tid >> 3;          // 0..31
    const int lc = (tid & 7) * 4;     // 0,4,..28

    for (int kc = 0; kc < DIM; kc += GBK) {
        __syncthreads();   // previous chunk's compute done before overwrite
        #pragma unroll
        for (int it = 0; it < 4; it++) {
            int r  = it * 32 + lr;
            int ga = row0 + r;                 // A row (u_s)
            int gb = col0 + r;                 // B row (v_s)
            uint2 zh = make_uint2(0u, 0u), zl = make_uint2(0u, 0u);
            if (ga < M6) {
                size_t o = (size_t)ga * DIM + kc + lc;
                zh = *(const uint2*)&g_hi[o];
                zl = *(const uint2*)&g_lo[o];
            }
            *(uint2*)&sAh[r][lc] = zh;
            *(uint2*)&sAl[r][lc] = zl;
            zh = make_uint2(0u, 0u); zl = make_uint2(0u, 0u);
            if (gb < M6) {
                size_t o = (size_t)(SIZE_U + gb) * DIM + kc + lc;
                zh = *(const uint2*)&g_hi[o];
                zl = *(const uint2*)&g_lo[o];
            }
            *(uint2*)&sBh[r][lc] = zh;
            *(uint2*)&sBl[r][lc] = zl;
        }
        __syncthreads();

        #pragma unroll
        for (int ks = 0; ks < 2; ks++) {
            const int kb = ks * 16;
            // A fragments: 4 m-frags x (hi,lo), ldmatrix x4 each
            unsigned ah[4][4], al[4][4];
            {
                const int arow = (lane & 15);
                const int acol = kb + ((lane & 16) >> 1);
                #pragma unroll
                for (int mf = 0; mf < 4; mf++) {
                    int r = wr + mf * 16 + arow;
                    ldsm4(ssa(&sAh[r][acol]), ah[mf][0], ah[mf][1], ah[mf][2], ah[mf][3]);
                    ldsm4(ssa(&sAl[r][acol]), al[mf][0], al[mf][1], al[mf][2], al[mf][3]);
                }
            }
            // B fragments: 2 x4 loads cover 4 n-frags (hi and lo)
            unsigned bh[2][4], bl[2][4];
            {
                const int brow = (lane & 7) + ((lane & 16) >> 1);
                const int bcol = kb + (lane & 8);
                #pragma unroll
                for (int nf2 = 0; nf2 < 2; nf2++) {
                    int r = wc + nf2 * 16 + brow;
                    ldsm4(ssa(&sBh[r][bcol]), bh[nf2][0], bh[nf2][1], bh[nf2][2], bh[nf2][3]);
                    ldsm4(ssa(&sBl[r][bcol]), bl[nf2][0], bl[nf2][1], bl[nf2][2], bl[nf2][3]);
                }
            }
            #pragma unroll
            for (int mf = 0; mf < 4; mf++)
                #pragma unroll
                for (int nf = 0; nf < 4; nf++) {
                    const int n2 = nf >> 1, h = (nf & 1) * 2;
                    mma16816(acc[mf][nf], ah[mf], bh[n2][h], bh[n2][h + 1]);
                    mma16816(acc[mf][nf], ah[mf], bl[n2][h], bl[n2][h + 1]);
                    mma16816(acc[mf][nf], al[mf], bh[n2][h], bh[n2][h + 1]);
                }
        }
    }

    // Epilogue: sigmoid + store. Accum frag: c0,c1 -> row g, cols 2t,2t+1;
    // c2,c3 -> row g+8.
    const int g = lane >> 2, t = lane & 3;
    #pragma unroll
    for (int mf = 0; mf < 4; mf++) {
        int r0 = row0 + wr + mf * 16 + g;
        #pragma unroll
        for (int nf = 0; nf < 4; nf++) {
            int c = col0 + wc + nf * 8 + t * 2;
            if (c >= M6) continue;
            if (r0 < M6) {
                float2 o;
                o.x = __fdividef(1.f, 1.f + __expf(-acc[mf][nf][0]));
                o.y = __fdividef(1.f, 1.f + __expf(-acc[mf][nf][1]));
                *(float2*)(C + (size_t)r0 * M6 + c) = o;
            }
            int r1 = r0 + 8;
            if (r1 < M6) {
                float2 o;
                o.x = __fdividef(1.f, 1.f + __expf(-acc[mf][nf][2]));
                o.y = __fdividef(1.f, 1.f + __expf(-acc[mf][nf][3]));
                *(float2*)(C + (size_t)r1 * M6 + c) = o;
            }
        }
    }
}

// ---------------------------------------------------------------------------
extern "C" void kernel_launch(void* const* d_in, const int* in_sizes, int n_in,
                              void* d_out, int out_size)
{
    const float* u   = (const float*)d_in[0];
    const float* v   = (const float*)d_in[1];
    const float* sim = (const float*)d_in[2];
    const void*  msk = d_in[3];
    float* out = (float*)d_out;

    detect_mask_kernel<<<1, 256>>>((const unsigned*)msk);
    topk_merge_kernel<<<N_TOTAL, 256>>>(u, v, sim, msk, out);

    dim3 g((M6 + GBN - 1) / GBN, (M6 + GBM - 1) / GBM);
    gemm_sigmoid_mma_kernel<<<g, 256>>>(out + OUT_X);
}

// round 8
// speedup vs baseline: 2.4614x; 1.4888x over previous
#include <cuda_runtime.h>
#include <cuda_bf16.h>
#include <cstdint>
#include <math.h>

// Problem constants
#define SIZE_U   6000
#define SIZE_V   6000
#define N_TOTAL  12000
#define DIM      256
#define KTOP     20
#define ROW_LEN  12000
#define CAP      1024

#define OUT_X    0ull
#define OUT_US   36000000ull
#define OUT_VS   37536000ull

// bf16 split scratch: row n in [0,12000) = concat(u_s, v_s), col in [0,256)
__device__ __nv_bfloat16 g_hi[(size_t)N_TOTAL * DIM];
__device__ __nv_bfloat16 g_lo[(size_t)N_TOTAL * DIM];

// ---------------------------------------------------------------------------
// Mask dtype detection (packed bool vs 32-bit word per element).
// ---------------------------------------------------------------------------
__device__ int g_mask_is_bool;

__global__ void detect_mask_kernel(const unsigned* __restrict__ m) {
    __shared__ int s_word, s_bool;
    if (threadIdx.x == 0) { s_word = 0; s_bool = 0; }
    __syncthreads();
    for (int i = threadIdx.x; i < 3000; i += blockDim.x) {
        unsigned w = m[i];
        if (w & 0xFEFEFEFEu)        atomicOr(&s_word, 1);
        else if (w & 0xFFFFFF00u)   atomicOr(&s_bool, 1);
    }
    __syncthreads();
    if (threadIdx.x == 0) g_mask_is_bool = (s_bool && !s_word) ? 1 : 0;
}

// ---------------------------------------------------------------------------
// Kernel 1: per-row top-20, weighted merge, mask select, bf16 hi/lo emit.
// Fast path selection = single-pass rank computation over ~84 candidates:
// rank_i = #{j: v_j > v_i or (v_j == v_i and idx_j < idx_i)} (total order ->
// unique ranks); rank < KTOP scatters straight into sorted-desc position.
// No per-round barriers, no tree reductions.
// ---------------------------------------------------------------------------
__global__ __launch_bounds__(256)
void topk_merge_kernel(const float* __restrict__ u, const float* __restrict__ v,
                       const float* __restrict__ sim, const void* __restrict__ mask,
                       float* __restrict__ out)
{
    const int n   = blockIdx.x;
    const int tid = threadIdx.x;

    bool keep;
    if (g_mask_is_bool) keep = ((const unsigned char*)mask)[n] != 0;
    else                keep = ((const unsigned*)mask)[n]      != 0;

    const float* feat = (n < SIZE_U) ? (u + (size_t)n * DIM)
                                     : (v + (size_t)(n - SIZE_U) * DIM);
    float* dst = (n < SIZE_U) ? (out + OUT_US + (size_t)n * DIM)
                              : (out + OUT_VS + (size_t)(n - SIZE_U) * DIM);

    if (keep) {
        float x = feat[tid];
        dst[tid] = x;
        __nv_bfloat16 h = __float2bfloat16(x);
        g_hi[(size_t)n * DIM + tid] = h;
        g_lo[(size_t)n * DIM + tid] = __float2bfloat16(x - __bfloat162float(h));
        return;
    }

    __shared__ float s_cval[CAP];
    __shared__ int   s_cidx[CAP];
    __shared__ int   s_cnt;
    __shared__ float s_rval[256];
    __shared__ int   s_ridx[256];
    __shared__ float s_selv[KTOP];
    __shared__ int   s_seli[KTOP];
    __shared__ float s_wsum;

    const float T0 = 0.993f;
    const float4* row4 = (const float4*)(sim + (size_t)n * ROW_LEN);

    if (tid == 0) s_cnt = 0;
    __syncthreads();

    for (int i = tid; i < ROW_LEN / 4; i += 256) {
        float4 sv = row4[i];
        if (sv.x > T0) { int p = atomicAdd(&s_cnt, 1); if (p < CAP) { s_cval[p] = sv.x; s_cidx[p] = 4*i;   } }
        if (sv.y > T0) { int p = atomicAdd(&s_cnt, 1); if (p < CAP) { s_cval[p] = sv.y; s_cidx[p] = 4*i+1; } }
        if (sv.z > T0) { int p = atomicAdd(&s_cnt, 1); if (p < CAP) { s_cval[p] = sv.z; s_cidx[p] = 4*i+2; } }
        if (sv.w > T0) { int p = atomicAdd(&s_cnt, 1); if (p < CAP) { s_cval[p] = sv.w; s_cidx[p] = 4*i+3; } }
    }
    __syncthreads();
    const int cnt = s_cnt;

    if (cnt >= KTOP && cnt <= CAP) {
        // ---- Fast path: single-pass rank selection ----
        float myv[4]; int myi[4]; int myrank[4];
        int nown = 0;
        #pragma unroll
        for (int q = 0; q < 4; q++) {
            int c = tid + q * 256;
            if (c < cnt) { myv[q] = s_cval[c]; myi[q] = s_cidx[c]; myrank[q] = 0; nown = q + 1; }
        }
        if (nown > 0) {
            for (int j = 0; j < cnt; j++) {
                float vj = s_cval[j]; int ij = s_cidx[j];   // LDS broadcast
                #pragma unroll
                for (int q = 0; q < 4; q++) {
                    if (q < nown &&
                        (vj > myv[q] || (vj == myv[q] && ij < myi[q]))) myrank[q]++;
                }
            }
            #pragma unroll
            for (int q = 0; q < 4; q++) {
                if (q < nown && myrank[q] < KTOP) {
                    s_selv[myrank[q]] = myv[q];
                    s_seli[myrank[q]] = myi[q];
                }
            }
        }
        __syncthreads();
    } else {
        // ---- Slow path (pathological data / overflow): 20 global argmax sweeps.
        const float* row = sim + (size_t)n * ROW_LEN;
        for (int j = 0; j < KTOP; j++) {
            float bv = -3e38f; int bi = 0x7fffffff;
            for (int i = tid; i < ROW_LEN; i += 256) {
                float vv = row[i];
                bool used = false;
                for (int q = 0; q < j; q++) if (s_seli[q] == i) used = true;
                if (!used && (vv > bv || (vv == bv && i < bi))) { bv = vv; bi = i; }
            }
            s_rval[tid] = bv; s_ridx[tid] = bi;
            __syncthreads();
            for (int s = 128; s; s >>= 1) {
                if (tid < s) {
                    float v2 = s_rval[tid + s]; int i2 = s_ridx[tid + s];
                    if (v2 > s_rval[tid] || (v2 == s_rval[tid] && i2 < s_ridx[tid])) {
                        s_rval[tid] = v2; s_ridx[tid] = i2;
                    }
                }
                __syncthreads();
            }
            if (tid == 0) { s_selv[j] = s_rval[0]; s_seli[j] = s_ridx[0]; }
            __syncthreads();
        }
    }

    if (tid == 0) {
        float s = 0.f;
        #pragma unroll
        for (int q = 0; q < KTOP; q++) s += s_selv[q];   // desc order, matches ref
        s_wsum = s;
    }
    __syncthreads();

    float acc = 0.f;
    #pragma unroll
    for (int q = 0; q < KTOP; q++) {
        int id = s_seli[q];
        const float* f = (id < SIZE_U) ? (u + (size_t)id * DIM)
                                       : (v + (size_t)(id - SIZE_U) * DIM);
        acc += s_selv[q] * f[tid];
    }
    float x = acc / s_wsum;
    dst[tid] = x;
    __nv_bfloat16 h = __float2bfloat16(x);
    g_hi[(size_t)n * DIM + tid] = h;
    g_lo[(size_t)n * DIM + tid] = __float2bfloat16(x - __bfloat162float(h));
}

// ---------------------------------------------------------------------------
// Kernel 2: C = sigmoid(A @ B^T) via bf16 split-fp32 mma.sync (tensor pipe).
// D = Ahi*Bhi + Ahi*Blo + Alo*Bhi (fp32 accumulate); lo*lo dropped.
// Tile: 128x128, BK=32, 8 warps (2x4), each warp 64x32 via m16n8k16.
// ---------------------------------------------------------------------------
#define M6   6000
#define GBM  128
#define GBN  128
#define GBK  32
#define LDT  40          // padded smem row stride (bf16) -> conflict-free LDSM

__device__ __forceinline__ unsigned ssa(const void* p) {
    return (unsigned)__cvta_generic_to_shared(p);
}

__device__ __forceinline__ void ldsm4(unsigned addr, unsigned& d0, unsigned& d1,
                                      unsigned& d2, unsigned& d3) {
    asm volatile("ldmatrix.sync.aligned.m8n8.x4.shared.b16 {%0,%1,%2,%3}, [%4];"
                 : "=r"(d0), "=r"(d1), "=r"(d2), "=r"(d3) : "r"(addr));
}

__device__ __forceinline__ void mma16816(float* c, const unsigned* a, unsigned b0, unsigned b1) {
    asm volatile(
        "mma.sync.aligned.m16n8k16.row.col.f32.bf16.bf16.f32 "
        "{%0,%1,%2,%3}, {%4,%5,%6,%7}, {%8,%9}, {%0,%1,%2,%3};"
        : "+f"(c[0]), "+f"(c[1]), "+f"(c[2]), "+f"(c[3])
        : "r"(a[0]), "r"(a[1]), "r"(a[2]), "r"(a[3]), "r"(b0), "r"(b1));
}

__global__ __launch_bounds__(256)
void gemm_sigmoid_mma_kernel(float* __restrict__ C)
{
    __shared__ __nv_bfloat16 sAh[GBM][LDT];
    __shared__ __nv_bfloat16 sAl[GBM][LDT];
    __shared__ __nv_bfloat16 sBh[GBN][LDT];
    __shared__ __nv_bfloat16 sBl[GBN][LDT];

    const int tid  = threadIdx.x;
    const int lane = tid & 31;
    const int wid  = tid >> 5;
    const int wr   = (wid >> 2) * 64;
    const int wc   = (wid & 3) * 32;
    const int row0 = blockIdx.y * GBM;
    const int col0 = blockIdx.x * GBN;

    float acc[4][4][4];
    #pragma unroll
    for (int i = 0; i < 4; i++)
        #pragma unroll
        for (int j = 0; j < 4; j++)
            #pragma unroll
            for (int q = 0; q < 4; q++) acc[i][j][q] = 0.f;

    const int lr = tid >> 3;
    const int lc = (tid & 7) * 4;

    for (int kc = 0; kc < DIM; kc += GBK) {
        __syncthreads();
        #pragma unroll
        for (int it = 0; it < 4; it++) {
            int r  = it * 32 + lr;
            int ga = row0 + r;
            int gb = col0 + r;
            uint2 zh = make_uint2(0u, 0u), zl = make_uint2(0u, 0u);
            if (ga < M6) {
                size_t o = (size_t)ga * DIM + kc + lc;
                zh = *(const uint2*)&g_hi[o];
                zl = *(const uint2*)&g_lo[o];
            }
            *(uint2*)&sAh[r][lc] = zh;
            *(uint2*)&sAl[r][lc] = zl;
            zh = make_uint2(0u, 0u); zl = make_uint2(0u, 0u);
            if (gb < M6) {
                size_t o = (size_t)(SIZE_U + gb) * DIM + kc + lc;
                zh = *(const uint2*)&g_hi[o];
                zl = *(const uint2*)&g_lo[o];
            }
            *(uint2*)&sBh[r][lc] = zh;
            *(uint2*)&sBl[r][lc] = zl;
        }
        __syncthreads();

        #pragma unroll
        for (int ks = 0; ks < 2; ks++) {
            const int kb = ks * 16;
            unsigned ah[4][4], al[4][4];
            {
                const int arow = (lane & 15);
                const int acol = kb + ((lane & 16) >> 1);
                #pragma unroll
                for (int mf = 0; mf < 4; mf++) {
                    int r = wr + mf * 16 + arow;
                    ldsm4(ssa(&sAh[r][acol]), ah[mf][0], ah[mf][1], ah[mf][2], ah[mf][3]);
                    ldsm4(ssa(&sAl[r][acol]), al[mf][0], al[mf][1], al[mf][2], al[mf][3]);
                }
            }
            unsigned bh[2][4], bl[2][4];
            {
                const int brow = (lane & 7) + ((lane & 16) >> 1);
                const int bcol = kb + (lane & 8);
                #pragma unroll
                for (int nf2 = 0; nf2 < 2; nf2++) {
                    int r = wc + nf2 * 16 + brow;
                    ldsm4(ssa(&sBh[r][bcol]), bh[nf2][0], bh[nf2][1], bh[nf2][2], bh[nf2][3]);
                    ldsm4(ssa(&sBl[r][bcol]), bl[nf2][0], bl[nf2][1], bl[nf2][2], bl[nf2][3]);
                }
            }
            #pragma unroll
            for (int mf = 0; mf < 4; mf++)
                #pragma unroll
                for (int nf = 0; nf < 4; nf++) {
                    const int n2 = nf >> 1, h = (nf & 1) * 2;
                    mma16816(acc[mf][nf], ah[mf], bh[n2][h], bh[n2][h + 1]);
                    mma16816(acc[mf][nf], ah[mf], bl[n2][h], bl[n2][h + 1]);
                    mma16816(acc[mf][nf], al[mf], bh[n2][h], bh[n2][h + 1]);
                }
        }
    }

    const int g = lane >> 2, t = lane & 3;
    #pragma unroll
    for (int mf = 0; mf < 4; mf++) {
        int r0 = row0 + wr + mf * 16 + g;
        #pragma unroll
        for (int nf = 0; nf < 4; nf++) {
            int c = col0 + wc + nf * 8 + t * 2;
            if (c >= M6) continue;
            if (r0 < M6) {
                float2 o;
                o.x = __fdividef(1.f, 1.f + __expf(-acc[mf][nf][0]));
                o.y = __fdividef(1.f, 1.f + __expf(-acc[mf][nf][1]));
                *(float2*)(C + (size_t)r0 * M6 + c) = o;
            }
            int r1 = r0 + 8;
            if (r1 < M6) {
                float2 o;
                o.x = __fdividef(1.f, 1.f + __expf(-acc[mf][nf][2]));
                o.y = __fdividef(1.f, 1.f + __expf(-acc[mf][nf][3]));
                *(float2*)(C + (size_t)r1 * M6 + c) = o;
            }
        }
    }
}

// ---------------------------------------------------------------------------
extern "C" void kernel_launch(void* const* d_in, const int* in_sizes, int n_in,
                              void* d_out, int out_size)
{
    const float* u   = (const float*)d_in[0];
    const float* v   = (const float*)d_in[1];
    const float* sim = (const float*)d_in[2];
    const void*  msk = d_in[3];
    float* out = (float*)d_out;

    detect_mask_kernel<<<1, 256>>>((const unsigned*)msk);
    topk_merge_kernel<<<N_TOTAL, 256>>>(u, v, sim, msk, out);

    dim3 g((M6 + GBN - 1) / GBN, (M6 + GBM - 1) / GBM);
    gemm_sigmoid_mma_kernel<<<g, 256>>>(out + OUT_X);
}

// round 12
// speedup vs baseline: 2.6337x; 1.0700x over previous
#include <cuda_runtime.h>
#include <cuda_bf16.h>
#include <cstdint>
#include <math.h>

// Problem constants
#define SIZE_U   6000
#define SIZE_V   6000
#define N_TOTAL  12000
#define DIM      256
#define KTOP     20
#define ROW_LEN  12000
#define CAP      1024

#define OUT_X    0ull
#define OUT_US   36000000ull
#define OUT_VS   37536000ull

// bf16 split scratch: row n in [0,12000) = concat(u_s, v_s), col in [0,256)
__device__ __nv_bfloat16 g_hi[(size_t)N_TOTAL * DIM];
__device__ __nv_bfloat16 g_lo[(size_t)N_TOTAL * DIM];

// ---------------------------------------------------------------------------
// Mask dtype detection (packed bool vs 32-bit word per element).
// ---------------------------------------------------------------------------
__device__ int g_mask_is_bool;

__global__ void detect_mask_kernel(const unsigned* __restrict__ m) {
    __shared__ int s_word, s_bool;
    if (threadIdx.x == 0) { s_word = 0; s_bool = 0; }
    __syncthreads();
    for (int i = threadIdx.x; i < 3000; i += blockDim.x) {
        unsigned w = m[i];
        if (w & 0xFEFEFEFEu)        atomicOr(&s_word, 1);
        else if (w & 0xFFFFFF00u)   atomicOr(&s_bool, 1);
    }
    __syncthreads();
    if (threadIdx.x == 0) g_mask_is_bool = (s_bool && !s_word) ? 1 : 0;
}

// ---------------------------------------------------------------------------
// Kernel 1: per-row top-20, weighted merge, mask select, bf16 hi/lo emit.
// Fast path: single-pass rank selection over ~84 threshold candidates.
// ---------------------------------------------------------------------------
__global__ __launch_bounds__(256)
void topk_merge_kernel(const float* __restrict__ u, const float* __restrict__ v,
                       const float* __restrict__ sim, const void* __restrict__ mask,
                       float* __restrict__ out)
{
    const int n   = blockIdx.x;
    const int tid = threadIdx.x;

    bool keep;
    if (g_mask_is_bool) keep = ((const unsigned char*)mask)[n] != 0;
    else                keep = ((const unsigned*)mask)[n]      != 0;

    const float* feat = (n < SIZE_U) ? (u + (size_t)n * DIM)
                                     : (v + (size_t)(n - SIZE_U) * DIM);
    float* dst = (n < SIZE_U) ? (out + OUT_US + (size_t)n * DIM)
                              : (out + OUT_VS + (size_t)(n - SIZE_U) * DIM);

    if (keep) {
        float x = feat[tid];
        dst[tid] = x;
        __nv_bfloat16 h = __float2bfloat16(x);
        g_hi[(size_t)n * DIM + tid] = h;
        g_lo[(size_t)n * DIM + tid] = __float2bfloat16(x - __bfloat162float(h));
        return;
    }

    __shared__ float s_cval[CAP];
    __shared__ int   s_cidx[CAP];
    __shared__ int   s_cnt;
    __shared__ float s_rval[256];
    __shared__ int   s_ridx[256];
    __shared__ float s_selv[KTOP];
    __shared__ int   s_seli[KTOP];
    __shared__ float s_wsum;

    const float T0 = 0.993f;
    const float4* row4 = (const float4*)(sim + (size_t)n * ROW_LEN);

    if (tid == 0) s_cnt = 0;
    __syncthreads();

    for (int i = tid; i < ROW_LEN / 4; i += 256) {
        float4 sv = row4[i];
        if (sv.x > T0) { int p = atomicAdd(&s_cnt, 1); if (p < CAP) { s_cval[p] = sv.x; s_cidx[p] = 4*i;   } }
        if (sv.y > T0) { int p = atomicAdd(&s_cnt, 1); if (p < CAP) { s_cval[p] = sv.y; s_cidx[p] = 4*i+1; } }
        if (sv.z > T0) { int p = atomicAdd(&s_cnt, 1); if (p < CAP) { s_cval[p] = sv.z; s_cidx[p] = 4*i+2; } }
        if (sv.w > T0) { int p = atomicAdd(&s_cnt, 1); if (p < CAP) { s_cval[p] = sv.w; s_cidx[p] = 4*i+3; } }
    }
    __syncthreads();
    const int cnt = s_cnt;

    if (cnt >= KTOP && cnt <= CAP) {
        float myv[4]; int myi[4]; int myrank[4];
        int nown = 0;
        #pragma unroll
        for (int q = 0; q < 4; q++) {
            int c = tid + q * 256;
            if (c < cnt) { myv[q] = s_cval[c]; myi[q] = s_cidx[c]; myrank[q] = 0; nown = q + 1; }
        }
        if (nown > 0) {
            for (int j = 0; j < cnt; j++) {
                float vj = s_cval[j]; int ij = s_cidx[j];
                #pragma unroll
                for (int q = 0; q < 4; q++) {
                    if (q < nown &&
                        (vj > myv[q] || (vj == myv[q] && ij < myi[q]))) myrank[q]++;
                }
            }
            #pragma unroll
            for (int q = 0; q < 4; q++) {
                if (q < nown && myrank[q] < KTOP) {
                    s_selv[myrank[q]] = myv[q];
                    s_seli[myrank[q]] = myi[q];
                }
            }
        }
        __syncthreads();
    } else {
        const float* row = sim + (size_t)n * ROW_LEN;
        for (int j = 0; j < KTOP; j++) {
            float bv = -3e38f; int bi = 0x7fffffff;
            for (int i = tid; i < ROW_LEN; i += 256) {
                float vv = row[i];
                bool used = false;
                for (int q = 0; q < j; q++) if (s_seli[q] == i) used = true;
                if (!used && (vv > bv || (vv == bv && i < bi))) { bv = vv; bi = i; }
            }
            s_rval[tid] = bv; s_ridx[tid] = bi;
            __syncthreads();
            for (int s = 128; s; s >>= 1) {
                if (tid < s) {
                    float v2 = s_rval[tid + s]; int i2 = s_ridx[tid + s];
                    if (v2 > s_rval[tid] || (v2 == s_rval[tid] && i2 < s_ridx[tid])) {
                        s_rval[tid] = v2; s_ridx[tid] = i2;
                    }
                }
                __syncthreads();
            }
            if (tid == 0) { s_selv[j] = s_rval[0]; s_seli[j] = s_ridx[0]; }
            __syncthreads();
        }
    }

    if (tid == 0) {
        float s = 0.f;
        #pragma unroll
        for (int q = 0; q < KTOP; q++) s += s_selv[q];
        s_wsum = s;
    }
    __syncthreads();

    float acc = 0.f;
    #pragma unroll
    for (int q = 0; q < KTOP; q++) {
        int id = s_seli[q];
        const float* f = (id < SIZE_U) ? (u + (size_t)id * DIM)
                                       : (v + (size_t)(id - SIZE_U) * DIM);
        acc += s_selv[q] * f[tid];
    }
    float x = acc / s_wsum;
    dst[tid] = x;
    __nv_bfloat16 h = __float2bfloat16(x);
    g_hi[(size_t)n * DIM + tid] = h;
    g_lo[(size_t)n * DIM + tid] = __float2bfloat16(x - __bfloat162float(h));
}

// ---------------------------------------------------------------------------
// Kernel 2: C = sigmoid(A @ B^T) via bf16 split-fp32 mma.sync, cp.async
// double-buffered. D = Ahi*Bhi + Ahi*Blo + Alo*Bhi, fp32 accumulate.
// Tile: 128x128, BK=32, 8 warps (2x4), each warp 64x32 via m16n8k16.
// Dynamic smem: 2 stages x (Ah,Al,Bh,Bl) x 128 x 40 bf16.
// ---------------------------------------------------------------------------
#define M6    6000
#define GBM   128
#define GBN   128
#define GBK   32
#define NCH   (DIM / GBK)        // 8
#define LDT   40                  // padded smem row stride (bf16), conflict-free LDSM
#define ARRB  (GBM * LDT * 2)     // bytes per array: 10240
#define STGB  (4 * ARRB)          // bytes per stage: 40960
#define SMEM_GEMM (2 * STGB)      // 81920

__device__ __forceinline__ unsigned ssa(const void* p) {
    return (unsigned)__cvta_generic_to_shared(p);
}
__device__ __forceinline__ void cp16(unsigned dst, const void* src, int bytes) {
    asm volatile("cp.async.cg.shared.global [%0], [%1], 16, %2;"
                 :: "r"(dst), "l"(src), "r"(bytes));
}
__device__ __forceinline__ void cp_commit() {
    asm volatile("cp.async.commit_group;" ::: "memory");
}
template <int N>
__device__ __forceinline__ void cp_wait() {
    asm volatile("cp.async.wait_group %0;" :: "n"(N) : "memory");
}
__device__ __forceinline__ void ldsm4(unsigned addr, unsigned& d0, unsigned& d1,
                                      unsigned& d2, unsigned& d3) {
    asm volatile("ldmatrix.sync.aligned.m8n8.x4.shared.b16 {%0,%1,%2,%3}, [%4];"
                 : "=r"(d0), "=r"(d1), "=r"(d2), "=r"(d3) : "r"(addr));
}
__device__ __forceinline__ void mma16816(float* c, const unsigned* a, unsigned b0, unsigned b1) {
    asm volatile(
        "mma.sync.aligned.m16n8k16.row.col.f32.bf16.bf16.f32 "
        "{%0,%1,%2,%3}, {%4,%5,%6,%7}, {%8,%9}, {%0,%1,%2,%3};"
        : "+f"(c[0]), "+f"(c[1]), "+f"(c[2]), "+f"(c[3])
        : "r"(a[0]), "r"(a[1]), "r"(a[2]), "r"(a[3]), "r"(b0), "r"(b1));
}

__global__ __launch_bounds__(256)
void gemm_sigmoid_mma_kernel(float* __restrict__ C)
{
    extern __shared__ char smem[];
    const unsigned sb = ssa(smem);

    const int tid  = threadIdx.x;
    const int lane = tid & 31;
    const int wid  = tid >> 5;
    const int wr   = (wid >> 2) * 64;   // warp row offset: 0 / 64
    const int wc   = (wid & 3) * 32;    // warp col offset: 0/32/64/96
    const int row0 = blockIdx.y * GBM;
    const int col0 = blockIdx.x * GBN;

    float acc[4][4][4];
    #pragma unroll
    for (int i = 0; i < 4; i++)
        #pragma unroll
        for (int j = 0; j < 4; j++)
            #pragma unroll
            for (int q = 0; q < 4; q++) acc[i][j][q] = 0.f;

    // cp.async loader: per array, 128 rows x 2 x 16B chunks/row... actually
    // 32 cols = 64B/row = 4 x 16B; 512 chunks/array; 2 per thread per array.
    auto load_stage = [&](int st, int kc) {
        const unsigned stbase = sb + st * STGB;
        #pragma unroll
        for (int arr = 0; arr < 4; arr++) {
            const __nv_bfloat16* gsrc = (arr & 1) ? g_lo : g_hi;
            const int rbase = (arr < 2) ? row0 : (SIZE_U + col0);
            const int rlim  = (arr < 2) ? (M6 - row0) : (M6 - col0);
            #pragma unroll
            for (int it = 0; it < 2; it++) {
                int idx = it * 256 + tid;         // 0..511
                int row = idx >> 2;               // 0..127
                int c4  = idx & 3;                // 16B group
                const void* src = gsrc + (size_t)(rbase + row) * DIM + kc + c4 * 8;
                unsigned dst = stbase + arr * ARRB + row * (LDT * 2) + c4 * 16;
                cp16(dst, src, (row < rlim) ? 16 : 0);
            }
        }
        cp_commit();
    };

    load_stage(0, 0);

    for (int c = 0; c < NCH; c++) {
        const int st = c & 1;
        if (c + 1 < NCH) load_stage(st ^ 1, (c + 1) * GBK);
        if (c + 1 < NCH) cp_wait<1>(); else cp_wait<0>();
        __syncthreads();

        const __nv_bfloat16* sAh = (const __nv_bfloat16*)(smem + st * STGB + 0 * ARRB);
        const __nv_bfloat16* sAl = (const __nv_bfloat16*)(smem + st * STGB + 1 * ARRB);
        const __nv_bfloat16* sBh = (const __nv_bfloat16*)(smem + st * STGB + 2 * ARRB);
        const __nv_bfloat16* sBl = (const __nv_bfloat16*)(smem + st * STGB + 3 * ARRB);

        #pragma unroll
        for (int ks = 0; ks < 2; ks++) {
            const int kb = ks * 16;
            unsigned ah[4][4], al[4][4];
            {
                const int arow = (lane & 15);
                const int acol = kb + ((lane & 16) >> 1);
                #pragma unroll
                for (int mf = 0; mf < 4; mf++) {
                    int r = wr + mf * 16 + arow;
                    ldsm4(ssa(sAh + r * LDT + acol), ah[mf][0], ah[mf][1], ah[mf][2], ah[mf][3]);
                    ldsm4(ssa(sAl + r * LDT + acol), al[mf][0], al[mf][1], al[mf][2], al[mf][3]);
                }
            }
            unsigned bh[2][4], bl[2][4];
            {
                const int brow = (lane & 7) + ((lane & 16) >> 1);
                const int bcol = kb + (lane & 8);
                #pragma unroll
                for (int nf2 = 0; nf2 < 2; nf2++) {
                    int r = wc + nf2 * 16 + brow;
                    ldsm4(ssa(sBh + r * LDT + bcol), bh[nf2][0], bh[nf2][1], bh[nf2][2], bh[nf2][3]);
                    ldsm4(ssa(sBl + r * LDT + bcol), bl[nf2][0], bl[nf2][1], bl[nf2][2], bl[nf2][3]);
                }
            }
            #pragma unroll
            for (int mf = 0; mf < 4; mf++)
                #pragma unroll
                for (int nf = 0; nf < 4; nf++) {
                    const int n2 = nf >> 1, h = (nf & 1) * 2;
                    mma16816(acc[mf][nf], ah[mf], bh[n2][h], bh[n2][h + 1]);
                    mma16816(acc[mf][nf], ah[mf], bl[n2][h], bl[n2][h + 1]);
                    mma16816(acc[mf][nf], al[mf], bh[n2][h], bh[n2][h + 1]);
                }
        }
        __syncthreads();   // all warps done with stage st before it is reloaded
    }

    // Epilogue: sigmoid + store.
    const int g = lane >> 2, t = lane & 3;
    #pragma unroll
    for (int mf = 0; mf < 4; mf++) {
        int r0 = row0 + wr + mf * 16 + g;
        #pragma unroll
        for (int nf = 0; nf < 4; nf++) {
            int c = col0 + wc + nf * 8 + t * 2;
            if (c >= M6) continue;
            if (r0 < M6) {
                float2 o;
                o.x = __fdividef(1.f, 1.f + __expf(-acc[mf][nf][0]));
                o.y = __fdividef(1.f, 1.f + __expf(-acc[mf][nf][1]));
                *(float2*)(C + (size_t)r0 * M6 + c) = o;
            }
            int r1 = r0 + 8;
            if (r1 < M6) {
                float2 o;
                o.x = __fdividef(1.f, 1.f + __expf(-acc[mf][nf][2]));
                o.y = __fdividef(1.f, 1.f + __expf(-acc[mf][nf][3]));
                *(float2*)(C + (size_t)r1 * M6 + c) = o;
            }
        }
    }
}

// ---------------------------------------------------------------------------
extern "C" void kernel_launch(void* const* d_in, const int* in_sizes, int n_in,
                              void* d_out, int out_size)
{
    const float* u   = (const float*)d_in[0];
    const float* v   = (const float*)d_in[1];
    const float* sim = (const float*)d_in[2];
    const void*  msk = d_in[3];
    float* out = (float*)d_out;

    detect_mask_kernel<<<1, 256>>>((const unsigned*)msk);
    topk_merge_kernel<<<N_TOTAL, 256>>>(u, v, sim, msk, out);

    cudaFuncSetAttribute(gemm_sigmoid_mma_kernel,
                         cudaFuncAttributeMaxDynamicSharedMemorySize, SMEM_GEMM);
    dim3 g((M6 + GBN - 1) / GBN, (M6 + GBM - 1) / GBM);
    gemm_sigmoid_mma_kernel<<<g, 256, SMEM_GEMM>>>(out + OUT_X);
}